// round 4
// baseline (speedup 1.0000x reference)
#include <cuda_runtime.h>
#include <cstdint>

// PolarToCartesianGrid: batched scatter-add into a voxel grid.
//
// R4: ONE persistent kernel, role-split blocks, software pipeline.
//   blocks [0, ZB)   : zero slab k (float4 streaming stores), publish done[k]
//   blocks [ZB, G)   : precompute per-cell warp-aggregation flags once (smem),
//                      then for each batch k: spin on done[k], scatter batch k
//                      with segmented shfl_down reduction + leader atomicAdd.
//   Zeroers have the lowest block IDs -> scheduled first, never wait -> no
//   deadlock. Static work split -> deterministic. Zero-store stream (DRAM
//   write pipe) overlaps scatter stream (L2 atomic pipe).

#define ZB 256          // zeroing blocks
#define SBK 484         // scatter blocks
#define NTHR 256
#define MAX_CHUNKS 9    // ceil((1M/256) / SBK)
#define MAX_SLABS 32

__device__ unsigned g_done[MAX_SLABS];

__global__ void reset_flags_kernel()
{
    if (threadIdx.x < MAX_SLABS) g_done[threadIdx.x] = 0;
}

__global__ __launch_bounds__(NTHR, 5)
void polar_pipeline_kernel(const float* __restrict__ polar,
                           const int*   __restrict__ vidx,
                           float*       __restrict__ out,
                           int n_cells, int batches, long long n_vox)
{
    const unsigned FULL = 0xFFFFFFFFu;
    const int tid  = threadIdx.x;
    const int lane = tid & 31;

    if ((int)blockIdx.x < ZB) {
        // ================= zeroing role =================
        float4* dst4base = (float4*)out;
        const long long n4 = n_vox >> 2;                  // n_vox % 4 == 0
        const float4 z = make_float4(0.f, 0.f, 0.f, 0.f);
        const long long tid0 = (long long)blockIdx.x * NTHR + tid;
        for (int k = 0; k < batches; ++k) {
            float4* dst = dst4base + (long long)k * n4;
            for (long long i = tid0; i < n4; i += (long long)ZB * NTHR)
                dst[i] = z;
            __threadfence();         // make slab-k stores globally visible
            __syncthreads();         // whole block done with slab k
            if (tid == 0) atomicAdd(&g_done[k], 1u);
        }
        return;
    }

    // ================= scatter role =================
    const int sb = (int)blockIdx.x - ZB;                  // 0..SBK-1
    const int n_groups = n_cells / NTHR;                  // 4096 full 256-groups

    __shared__ int           s_idx[MAX_CHUNKS * NTHR];
    __shared__ unsigned char s_flg[MAX_CHUNKS * NTHR];

    // ---- phase A: per-cell index + aggregation flags, computed ONCE ----
    // Equal voxel indices along az form contiguous lane runs (arc through the
    // grid); segmented shfl_down reduction over runs needs only: head bit +
    // "lane+d is same segment" bits for d=1,2,4,8,16. Rare non-contiguous
    // duplicates simply produce extra leader atomics (still correct).
    #pragma unroll
    for (int c = 0; c < MAX_CHUNKS; ++c) {
        const int grp = c * SBK + sb;
        if (grp >= n_groups) break;
        const int cell = grp * NTHR + tid;
        const int idx = vidx[cell];
        const int prev = __shfl_up_sync(FULL, idx, 1);
        unsigned f = (lane == 0 || prev != idx) ? 1u : 0u;   // head
        int t;
        t = __shfl_down_sync(FULL, idx, 1);  if (lane + 1  < 32 && t == idx) f |= 2u;
        t = __shfl_down_sync(FULL, idx, 2);  if (lane + 2  < 32 && t == idx) f |= 4u;
        t = __shfl_down_sync(FULL, idx, 4);  if (lane + 4  < 32 && t == idx) f |= 8u;
        t = __shfl_down_sync(FULL, idx, 8);  if (lane + 8  < 32 && t == idx) f |= 16u;
        t = __shfl_down_sync(FULL, idx, 16); if (lane + 16 < 32 && t == idx) f |= 32u;
        s_idx[c * NTHR + tid] = idx;
        s_flg[c * NTHR + tid] = (unsigned char)f;
    }
    __syncthreads();

    // ---- phase B: per batch, gated on that slab's zeroing ----
    for (int k = 0; k < batches; ++k) {
        if (tid == 0) {
            volatile unsigned* dp = &g_done[k];
            while (*dp < (unsigned)ZB) __nanosleep(64);
            __threadfence();         // acquire: order after zeroers' stores
        }
        __syncthreads();

        const float* pk = polar + (size_t)k * n_cells;
        float* ok = out + (long long)k * n_vox;

        #pragma unroll
        for (int c = 0; c < MAX_CHUNKS; ++c) {
            const int grp = c * SBK + sb;
            if (grp >= n_groups) break;
            const int cell = grp * NTHR + tid;
            float v = __ldg(pk + cell);
            const unsigned f = s_flg[c * NTHR + tid];
            float t;
            // segmented suffix reduction: head lane ends with its run's sum
            t = __shfl_down_sync(FULL, v, 1);  if (f & 2u)  v += t;
            t = __shfl_down_sync(FULL, v, 2);  if (f & 4u)  v += t;
            t = __shfl_down_sync(FULL, v, 4);  if (f & 8u)  v += t;
            t = __shfl_down_sync(FULL, v, 8);  if (f & 16u) v += t;
            t = __shfl_down_sync(FULL, v, 16); if (f & 32u) v += t;
            if (f & 1u) atomicAdd(ok + s_idx[c * NTHR + tid], v);  // RED, no return
        }
    }
}

extern "C" void kernel_launch(void* const* d_in, const int* in_sizes, int n_in,
                              void* d_out, int out_size)
{
    const float* polar = (const float*)d_in[0];            // [B,1,El,R,Az] f32
    const int*   vidx  = (const int*)d_in[1];              // [El*R*Az] int32
    float*       out   = (float*)d_out;                    // [B,1,Z,Y,X] f32

    const int n_cells = in_sizes[1];                       // 1,048,576
    int batches = in_sizes[0] / n_cells;                   // 16
    if (batches > MAX_SLABS) batches = MAX_SLABS;
    const long long n_vox = (long long)out_size / batches; // 8,192,000

    reset_flags_kernel<<<1, MAX_SLABS>>>();
    polar_pipeline_kernel<<<ZB + SBK, NTHR>>>(polar, vidx, out,
                                              n_cells, batches, n_vox);
}

// round 5
// speedup vs baseline: 1.5276x; 1.5276x over previous
#include <cuda_runtime.h>
#include <cstdint>

// PolarToCartesianGrid: batched scatter-add into a cartesian voxel grid.
//
// R5: fork/join graph pipeline.
//   stream 0 : flag-precompute kernel, then 16 per-slab memsets (engine-rate
//              zeroing, ~5.5us each), one event after each memset.
//   stream s2: scatter(batch k) gated on memset(slab k) via event edge.
//              Scatter is cheap (~3us/batch) because the warp-segmented
//              aggregation flags are precomputed once into device scratch.
//   join: event on s2 -> wait on stream 0.
// Streams/events are created inside kernel_launch (called only for the
// correctness run and the capture run; never during replays).

#define NTHR 256
#define MAX_CELLS (1 << 21)
#define MAX_BATCHES 32

__device__ unsigned char g_flags[MAX_CELLS];

// 6-bit flags per cell for warp-segmented suffix reduction:
//   bit0: segment head (first lane of a run of equal voxel indices)
//   bit{1..5}: lane+d (d=1,2,4,8,16) holds the same voxel index
__global__ void precompute_flags_kernel(const int* __restrict__ vidx, int n_cells)
{
    const int cell = blockIdx.x * blockDim.x + threadIdx.x;
    if (cell >= n_cells) return;
    const unsigned FULL = 0xFFFFFFFFu;
    const int lane = threadIdx.x & 31;

    const int idx = vidx[cell];
    const int prev = __shfl_up_sync(FULL, idx, 1);
    unsigned f = (lane == 0 || prev != idx) ? 1u : 0u;
    int t;
    t = __shfl_down_sync(FULL, idx, 1);  if (lane + 1  < 32 && t == idx) f |= 2u;
    t = __shfl_down_sync(FULL, idx, 2);  if (lane + 2  < 32 && t == idx) f |= 4u;
    t = __shfl_down_sync(FULL, idx, 4);  if (lane + 4  < 32 && t == idx) f |= 8u;
    t = __shfl_down_sync(FULL, idx, 8);  if (lane + 8  < 32 && t == idx) f |= 16u;
    t = __shfl_down_sync(FULL, idx, 16); if (lane + 16 < 32 && t == idx) f |= 32u;
    g_flags[cell] = (unsigned char)f;
}

// one batch: segmented suffix reduction over precomputed flags + leader RED
__global__ void scatter_batch_kernel(const float* __restrict__ polar_b,
                                     const int*   __restrict__ vidx,
                                     float*       __restrict__ out_b,
                                     int n_cells)
{
    const int cell = blockIdx.x * blockDim.x + threadIdx.x;
    if (cell >= n_cells) return;               // n_cells % 256 == 0
    const unsigned FULL = 0xFFFFFFFFu;

    const unsigned f = g_flags[cell];
    float v = __ldg(polar_b + cell);
    float t;
    t = __shfl_down_sync(FULL, v, 1);  if (f & 2u)  v += t;
    t = __shfl_down_sync(FULL, v, 2);  if (f & 4u)  v += t;
    t = __shfl_down_sync(FULL, v, 4);  if (f & 8u)  v += t;
    t = __shfl_down_sync(FULL, v, 8);  if (f & 16u) v += t;
    t = __shfl_down_sync(FULL, v, 16); if (f & 32u) v += t;
    if (f & 1u) atomicAdd(out_b + vidx[cell], v);
}

extern "C" void kernel_launch(void* const* d_in, const int* in_sizes, int n_in,
                              void* d_out, int out_size)
{
    const float* polar = (const float*)d_in[0];            // [B,1,El,R,Az] f32
    const int*   vidx  = (const int*)d_in[1];              // [El*R*Az] int32
    float*       out   = (float*)d_out;                    // [B,1,Z,Y,X] f32

    const int n_cells = in_sizes[1];                       // 1,048,576
    int batches = in_sizes[0] / n_cells;                   // 16
    if (batches > MAX_BATCHES) batches = MAX_BATCHES;
    const long long n_vox = (long long)out_size / batches; // 8,192,000

    const int blocks = (n_cells + NTHR - 1) / NTHR;

    // per-call resources (host-side only; kernel_launch runs just twice)
    cudaStream_t s2 = nullptr;
    cudaEvent_t  evZ[MAX_BATCHES] = {};
    cudaEvent_t  evJoin = nullptr;
    bool multi = (n_cells <= MAX_CELLS) &&
                 (cudaStreamCreateWithFlags(&s2, cudaStreamNonBlocking) == cudaSuccess);
    for (int i = 0; i < batches && multi; ++i)
        multi = (cudaEventCreateWithFlags(&evZ[i], cudaEventDisableTiming) == cudaSuccess);
    if (multi)
        multi = (cudaEventCreateWithFlags(&evJoin, cudaEventDisableTiming) == cudaSuccess);

    // flags once per launch (stream 0, before the first memset/event)
    precompute_flags_kernel<<<blocks, NTHR>>>(vidx, n_cells);

    if (multi) {
        // memset chain on capture stream; event after each slab
        for (int b = 0; b < batches; ++b) {
            cudaMemsetAsync(out + (long long)b * n_vox, 0,
                            (size_t)n_vox * sizeof(float), 0);
            cudaEventRecord(evZ[b], 0);
        }
        // forked stream: scatter(b) gated on memset(b) (and transitively on
        // the flag precompute, which precedes evZ[b] on stream 0)
        for (int b = 0; b < batches; ++b) {
            cudaStreamWaitEvent(s2, evZ[b], 0);
            scatter_batch_kernel<<<blocks, NTHR, 0, s2>>>(
                polar + (size_t)b * n_cells, vidx,
                out + (long long)b * n_vox, n_cells);
        }
        cudaEventRecord(evJoin, s2);
        cudaStreamWaitEvent(0, evJoin, 0);
    } else {
        // serial fallback (~R1): one big memset + per-batch scatters
        cudaMemsetAsync(d_out, 0, (size_t)out_size * sizeof(float), 0);
        for (int b = 0; b < batches; ++b)
            scatter_batch_kernel<<<blocks, NTHR>>>(
                polar + (size_t)b * n_cells, vidx,
                out + (long long)b * n_vox, n_cells);
    }
}

// round 6
// speedup vs baseline: 1.5500x; 1.0146x over previous
#include <cuda_runtime.h>
#include <cstdint>

// PolarToCartesianGrid: batched scatter-add into a cartesian voxel grid.
//
// R6: fork/join graph pipeline with grouped, packed scatters.
//   stream 0 : pack kernel (idx[23b] | flags[6b] -> u32, once), then 16
//              per-slab memsets (engine-rate zeroing), event after each.
//   stream s2: scatter kernel per PAIR of batches, gated on the second
//              slab's memset event. Packed load amortized across the pair;
//              both polar loads issued up front for MLP.
//   join back to stream 0.
// Streams/events created inside kernel_launch (runs only twice: correctness
// + capture), never at static-init and never during replays.

#define NTHR 256
#define MAX_CELLS (1 << 21)
#define MAX_BATCHES 32
#define GROUP 2

__device__ unsigned g_packed[MAX_CELLS];   // idx | (flags<<23)

// flags: bit0 = segment head; bit{1..5} = lane+d (d=1,2,4,8,16) same index
__global__ void pack_kernel(const int* __restrict__ vidx, int n_cells)
{
    const int cell = blockIdx.x * blockDim.x + threadIdx.x;
    if (cell >= n_cells) return;
    const unsigned FULL = 0xFFFFFFFFu;
    const int lane = threadIdx.x & 31;

    const int idx = vidx[cell];
    const int prev = __shfl_up_sync(FULL, idx, 1);
    unsigned f = (lane == 0 || prev != idx) ? 1u : 0u;
    int t;
    t = __shfl_down_sync(FULL, idx, 1);  if (lane + 1  < 32 && t == idx) f |= 2u;
    t = __shfl_down_sync(FULL, idx, 2);  if (lane + 2  < 32 && t == idx) f |= 4u;
    t = __shfl_down_sync(FULL, idx, 4);  if (lane + 4  < 32 && t == idx) f |= 8u;
    t = __shfl_down_sync(FULL, idx, 8);  if (lane + 8  < 32 && t == idx) f |= 16u;
    t = __shfl_down_sync(FULL, idx, 16); if (lane + 16 < 32 && t == idx) f |= 32u;
    g_packed[cell] = (unsigned)idx | (f << 23);
}

// scatter a group of `nb` (1..GROUP) consecutive batches
__global__ void scatter_group_kernel(const float* __restrict__ polar_g, // batch b0
                                     float*       __restrict__ out_g,   // slab b0
                                     int n_cells, long long n_vox, int nb)
{
    const int cell = blockIdx.x * blockDim.x + threadIdx.x;
    if (cell >= n_cells) return;               // n_cells % 256 == 0
    const unsigned FULL = 0xFFFFFFFFu;

    const unsigned p   = g_packed[cell];
    const unsigned idx = p & 0x7FFFFFu;
    const unsigned f   = p >> 23;

    // issue all polar loads up front (MLP)
    float v0 = __ldg(polar_g + cell);
    float v1 = (nb > 1) ? __ldg(polar_g + n_cells + cell) : 0.f;

    float t0, t1;   // interleaved segmented suffix reductions (ILP)
    t0 = __shfl_down_sync(FULL, v0, 1);  t1 = __shfl_down_sync(FULL, v1, 1);
    if (f & 2u)  { v0 += t0; v1 += t1; }
    t0 = __shfl_down_sync(FULL, v0, 2);  t1 = __shfl_down_sync(FULL, v1, 2);
    if (f & 4u)  { v0 += t0; v1 += t1; }
    t0 = __shfl_down_sync(FULL, v0, 4);  t1 = __shfl_down_sync(FULL, v1, 4);
    if (f & 8u)  { v0 += t0; v1 += t1; }
    t0 = __shfl_down_sync(FULL, v0, 8);  t1 = __shfl_down_sync(FULL, v1, 8);
    if (f & 16u) { v0 += t0; v1 += t1; }
    t0 = __shfl_down_sync(FULL, v0, 16); t1 = __shfl_down_sync(FULL, v1, 16);
    if (f & 32u) { v0 += t0; v1 += t1; }

    if (f & 1u) {
        atomicAdd(out_g + idx, v0);
        if (nb > 1) atomicAdd(out_g + n_vox + idx, v1);
    }
}

// fallback: per-batch scatter with inline match (no packing assumptions)
__global__ void scatter_fallback_kernel(const float* __restrict__ polar_b,
                                        const int*   __restrict__ vidx,
                                        float*       __restrict__ out_b,
                                        int n_cells)
{
    const int cell = blockIdx.x * blockDim.x + threadIdx.x;
    if (cell >= n_cells) return;
    const unsigned FULL = 0xFFFFFFFFu;
    const int lane = threadIdx.x & 31;
    const int idx = vidx[cell];
    float v = __ldg(polar_b + cell);
    const unsigned peers = __match_any_sync(FULL, idx);
    const int rank = __popc(peers & ((1u << lane) - 1u));
    const unsigned s1  = __fns(peers, lane, 2);
    const unsigned s2  = __fns(peers, lane, 3);
    const unsigned s4  = __fns(peers, lane, 5);
    const unsigned s8  = __fns(peers, lane, 9);
    const unsigned s16 = __fns(peers, lane, 17);
    float t;
    t = __shfl_sync(FULL, v, s1  & 31); if (s1  < 32) v += t;
    t = __shfl_sync(FULL, v, s2  & 31); if (s2  < 32) v += t;
    t = __shfl_sync(FULL, v, s4  & 31); if (s4  < 32) v += t;
    t = __shfl_sync(FULL, v, s8  & 31); if (s8  < 32) v += t;
    t = __shfl_sync(FULL, v, s16 & 31); if (s16 < 32) v += t;
    if (rank == 0) atomicAdd(out_b + idx, v);
}

extern "C" void kernel_launch(void* const* d_in, const int* in_sizes, int n_in,
                              void* d_out, int out_size)
{
    const float* polar = (const float*)d_in[0];            // [B,1,El,R,Az] f32
    const int*   vidx  = (const int*)d_in[1];              // [El*R*Az] int32
    float*       out   = (float*)d_out;                    // [B,1,Z,Y,X] f32

    const int n_cells = in_sizes[1];                       // 1,048,576
    int batches = in_sizes[0] / n_cells;                   // 16
    if (batches > MAX_BATCHES) batches = MAX_BATCHES;
    const long long n_vox = (long long)out_size / batches; // 8,192,000

    const int blocks = (n_cells + NTHR - 1) / NTHR;
    const bool packable = (n_cells <= MAX_CELLS) && (n_vox < (1LL << 23));

    cudaStream_t s2 = nullptr;
    cudaEvent_t  evZ[MAX_BATCHES] = {};
    cudaEvent_t  evJoin = nullptr;
    bool multi = packable &&
                 (cudaStreamCreateWithFlags(&s2, cudaStreamNonBlocking) == cudaSuccess);
    for (int i = 0; i < batches && multi; ++i)
        multi = (cudaEventCreateWithFlags(&evZ[i], cudaEventDisableTiming) == cudaSuccess);
    if (multi)
        multi = (cudaEventCreateWithFlags(&evJoin, cudaEventDisableTiming) == cudaSuccess);

    if (multi) {
        pack_kernel<<<blocks, NTHR>>>(vidx, n_cells);
        for (int b = 0; b < batches; ++b) {
            cudaMemsetAsync(out + (long long)b * n_vox, 0,
                            (size_t)n_vox * sizeof(float), 0);
            cudaEventRecord(evZ[b], 0);
        }
        for (int b0 = 0; b0 < batches; b0 += GROUP) {
            const int nb = (batches - b0 < GROUP) ? (batches - b0) : GROUP;
            cudaStreamWaitEvent(s2, evZ[b0 + nb - 1], 0);
            scatter_group_kernel<<<blocks, NTHR, 0, s2>>>(
                polar + (size_t)b0 * n_cells,
                out + (long long)b0 * n_vox,
                n_cells, n_vox, nb);
        }
        cudaEventRecord(evJoin, s2);
        cudaStreamWaitEvent(0, evJoin, 0);
    } else {
        cudaMemsetAsync(d_out, 0, (size_t)out_size * sizeof(float), 0);
        for (int b = 0; b < batches; ++b)
            scatter_fallback_kernel<<<blocks, NTHR>>>(
                polar + (size_t)b * n_cells, vidx,
                out + (long long)b * n_vox, n_cells);
    }
}